// round 16
// baseline (speedup 1.0000x reference)
#include <cuda_runtime.h>
#include <cstdint>

// Shapes: depth_map/x_ray [8,1,512,512] fp32 -> out [8,1,128,128,128] fp32
#define NB    8
#define INHW  512
#define RHW   128   // resized H=W
#define ND    128   // depth bins
#define SROWS 134   // histogram rows: depth -3..130 at offset +3

// Intermediate buffers (device globals: allocation-free scratch)
__device__ float g_xr[NB * RHW * RHW];
__device__ int   g_dr[NB * RHW * RHW];   // pre-scaled row offset: (d_idx+3)*128

// ---------------------------------------------------------------------------
// float4 helpers with immediate weights (ptxas -> FFMA-imm, rt 1/SMSP)
// ---------------------------------------------------------------------------
__device__ __forceinline__ float4 add4(float4 a, float4 b) {
    return make_float4(a.x + b.x, a.y + b.y, a.z + b.z, a.w + b.w);
}
__device__ __forceinline__ float4 fma4s(float4 a, float w, float4 c) {
    return make_float4(fmaf(a.x, w, c.x), fmaf(a.y, w, c.y),
                       fmaf(a.z, w, c.z), fmaf(a.w, w, c.w));
}
__device__ __forceinline__ float4 mul4s(float4 a, float w) {
    return make_float4(a.x * w, a.y * w, a.z * w, a.w * w);
}

// ---------------------------------------------------------------------------
// Kernel 1: jax.image.resize(bilinear, antialias=True) 512->128 both arrays,
// plus depth->index conversion. Block = (h, b), 256 threads:
//   half = tid>>7 owns 4 of the 8 vertical taps; wt = tid&127 = float4 col.
// Horizontal pass: half 0 -> depth (g_dr pre-scaled row), half 1 -> x_ray.
// Raw triangle weights {1,3,5,7,7,5,3,1}/8, normalized by in-range sum.
// ---------------------------------------------------------------------------
__global__ __launch_bounds__(256) void resize_kernel(const float* __restrict__ depth,
                                                     const float* __restrict__ xray) {
    const int tid  = threadIdx.x;
    const int half = tid >> 7;
    const int wt   = tid & 127;
    const int h    = blockIdx.x;
    const int b    = blockIdx.y;

    __shared__ float tmpd[2][INHW];
    __shared__ float tmpx[2][INHW];

    const float RW[8] = {0.125f, 0.375f, 0.625f, 0.875f,
                         0.875f, 0.625f, 0.375f, 0.125f};

    float4 ad = make_float4(0.f, 0.f, 0.f, 0.f);
    float4 ax = make_float4(0.f, 0.f, 0.f, 0.f);

    #pragma unroll
    for (int tt = 0; tt < 4; ++tt) {
        int t = half * 4 + tt;
        int j = 4 * h - 2 + t;                 // input row (uniform per warp)
        if ((unsigned)j >= (unsigned)INHW) continue;
        float wv = RW[t];
        const float4* drow = (const float4*)(depth + ((size_t)b * INHW + j) * INHW);
        const float4* xrow = (const float4*)(xray  + ((size_t)b * INHW + j) * INHW);
        float4 dv = drow[wt];
        float4 xv = xrow[wt];
        ad = fma4s(dv, wv, ad);
        ax = fma4s(xv, wv, ax);
    }
    ((float4*)tmpd[half])[wt] = ad;
    ((float4*)tmpx[half])[wt] = ax;

    float wsv = 0.f;
    #pragma unroll
    for (int t = 0; t < 8; ++t) {
        int j = 4 * h - 2 + t;
        if ((unsigned)j < (unsigned)INHW) wsv += RW[t];
    }
    __syncthreads();

    const float* buf0 = half ? tmpx[0] : tmpd[0];
    const float* buf1 = half ? tmpx[1] : tmpd[1];

    float acc = 0.f, wsh = 0.f;
    #pragma unroll
    for (int t = 0; t < 8; ++t) {
        int c = 4 * wt - 2 + t;                // input col
        if ((unsigned)c < (unsigned)INHW) {
            float wv = RW[t];
            wsh += wv;
            acc = fmaf(wv, buf0[c] + buf1[c], acc);
        }
    }
    float val = acc / (wsv * wsh);

    int idx = (b * RHW + h) * RHW + wt;
    if (half == 0) {
        // d_idx = clip(int((depth/100)*127), 0, 127); store pre-scaled row
        int di = (int)((val / 100.f) * 127.f);
        di = di < 0 ? 0 : (di > ND - 1 ? ND - 1 : di);
        g_dr[idx] = (di + 3) * 128;
    } else {
        g_xr[idx] = val;
    }
}

// ---------------------------------------------------------------------------
// Kernel 2: fused gaussian depth splat + 3x3x3 avg pool (/27, include_pad):
//   s[d][w] = 9-neighbor weighted histogram (3x3 spatial pool folded in)
//   out[d]  = (W7 (*) s)[d], W7 = box3 (*) gauss5 with /27 folded in, minus
//   exact corrections at d=0 / d=127 for the excluded pool taps p[-1]/p[128]
//   (p = gauss5 (*) s on [0,127] == the reference's splat-target clipping).
// Block = (h, b), 512 threads, 68KB tile s[134][128] d-major (bank = w%32:
// conflict-free everywhere).
//   Scatter: all 1152 RMW tasks (9 neighbors x 128 cols) spread over 512
//   threads via smem atomicAdd -> no serial chains, no idle warps.
//   Gather: thread = (wq = tid&31 -> 4 w's, dq = tid>>5 -> 8 depths);
//   7-row float4 sliding window, FFMA-imm math, LDS.128 in, STG.128 out.
// __launch_bounds__(512,3): cap regs at ~42 so 3 blocks/SM (smem-limited).
// ---------------------------------------------------------------------------
__global__ __launch_bounds__(512, 3) void splat_pool_kernel(float* __restrict__ out) {
    extern __shared__ float s[];               // [SROWS][128], 68608 B
    __shared__ float sxs[3][130];
    __shared__ int   sdr[3][130];

    const int h   = blockIdx.x;
    const int b   = blockIdx.y;
    const int tid = threadIdx.x;

    // Zero the histogram tile (float4)
    float4* s4 = (float4*)s;
    for (int i = tid; i < SROWS * 128 / 4; i += 512)
        s4[i] = make_float4(0.f, 0.f, 0.f, 0.f);

    // Halo load: 3 rows x 130 cols (zero xv out of range -> harmless RMW)
    if (tid < 3 * 130) {
        int dh = tid / 130, wi = tid - dh * 130;
        int hh = h + dh - 1, ww = wi - 1;
        bool v = ((unsigned)hh < (unsigned)RHW) && ((unsigned)ww < (unsigned)RHW);
        int idx = (b * RHW + (v ? hh : 0)) * RHW + (v ? ww : 0);
        sxs[dh][wi] = v ? g_xr[idx] : 0.f;
        sdr[dh][wi] = v ? g_dr[idx] : 3 * 128;
    }
    __syncthreads();

    // Scatter: 1152 tasks = (neighbor r 0..8) x (column w 0..127), spread
    // over all threads with smem atomicAdd (banks w%32: conflict-free).
    #pragma unroll
    for (int t = 0; t < 3; ++t) {
        int task = tid + t * 512;
        if (task < 9 * 128) {
            int r = task >> 7;                 // neighbor index
            int w = task & 127;
            int dh = r / 3, dw = r - dh * 3;
            float xv = sxs[dh][w + dw];
            int   ro = sdr[dh][w + dw];
            atomicAdd(&s[ro + w], xv);
        }
    }
    __syncthreads();

    // 7-tap combined weights (symmetric), 1/27 folded in — immediates
    const float e1 = 0.60653065971263342f;     // exp(-0.5)
    const float e2 = 0.13533528323661270f;     // exp(-2)
    const float G1 = e1 / 27.f, G2 = e2 / 27.f;
    const float W0 = 1.f / 27.f + 2.f * G1;
    const float W1 = 1.f / 27.f + G1 + G2;
    const float W2 = G1 + G2;
    const float W3 = G2;

    const int wq = tid & 31;                   // float4 w-group
    const int dq = tid >> 5;                   // 16 depth groups x 8 depths
    const int d0 = dq << 3;

    const float4* srow = (const float4*)s;     // row = 32 float4

    float4 v[7];                               // rows d0..d0+6 (= s[d0-3..d0+3])
    #pragma unroll
    for (int k = 0; k < 7; ++k) v[k] = srow[(d0 + k) * 32 + wq];

    float* op = out + (size_t)b * (ND * RHW * RHW) + (size_t)h * RHW
                    + (wq << 2) + (size_t)d0 * (RHW * RHW);

    #pragma unroll
    for (int i = 0; i < 8; ++i) {
        // conv: v[0..6] = s[d-3 .. d+3]
        float4 c = mul4s(v[3], W0);
        c = fma4s(add4(v[2], v[4]), W1, c);
        c = fma4s(add4(v[1], v[5]), W2, c);
        c = fma4s(add4(v[0], v[6]), W3, c);
        if (dq == 0 && i == 0) {               // d==0: remove p[-1] = G1*s[0]+G2*s[1]
            c = fma4s(v[3], -G1, c);
            c = fma4s(v[4], -G2, c);
        }
        if (dq == 15 && i == 7) {              // d==127: remove p[128] = G1*s[127]+G2*s[126]
            c = fma4s(v[3], -G1, c);
            c = fma4s(v[2], -G2, c);
        }
        *(float4*)op = c;                      // STG.128, coalesced across warp
        op += RHW * RHW;

        if (i < 7) {
            #pragma unroll
            for (int k = 0; k < 6; ++k) v[k] = v[k + 1];
            v[6] = srow[(d0 + i + 7) * 32 + wq];   // max row 133 = SROWS-1
        }
    }
}

// ---------------------------------------------------------------------------
extern "C" void kernel_launch(void* const* d_in, const int* in_sizes, int n_in,
                              void* d_out, int out_size) {
    const float* depth = (const float*)d_in[0];   // [8,1,512,512] fp32
    const float* xray  = (const float*)d_in[1];   // [8,1,512,512] fp32
    float* out = (float*)d_out;                   // [8,1,128,128,128] fp32

    (void)in_sizes; (void)n_in; (void)out_size;

    cudaFuncSetAttribute(splat_pool_kernel,
                         cudaFuncAttributeMaxDynamicSharedMemorySize,
                         SROWS * 128 * (int)sizeof(float));

    dim3 grid(RHW, NB);
    resize_kernel<<<grid, 256>>>(depth, xray);
    splat_pool_kernel<<<grid, 512, SROWS * 128 * sizeof(float)>>>(out);
}